// round 13
// baseline (speedup 1.0000x reference)
#include <cuda_runtime.h>
#include <stdint.h>

// TDGSPooling2d: gumbel-softmax hard pooling over 2x2 patches (forward = argmax).
// out[b,c,ho,wo] = x_patch[argmax_k(x_patch[k]/temp[c,ho,wo] + g_k)]
// Noise: JAX partitionable threefry: bits[i] = o0^o1,
//   (o0,o1) = threefry2x32(key=(0,42), counter=(0,i))
//
// R13: alu-pipe is the measured wall (89.8%, alu-equiv ~128us since R4).
// Re-apply the R10 tail fold NOW that alu binds: per hash, final-xor +
// bit-prep (x0^x1, >>9, |0x3f800000 = 3 alu) -> umulhi(x0,2^23),
// umulhi(x1,2^23) [fma pipe; v>>9 == mulhi(v,2^23)] + ONE LOP3
// (h0^h1)|C (lut 0xBE) = 1 alu. -32 alu/thread (~-5% of the wall).
// Noise bits identical -> rel_err must stay exactly 1.620238e-4.

#define QC 12845056u   // x element stride AND counter stride per quarter (=4*QO)
#define QO 3211264u    // output element stride per batch-quarter (8*401408)

// add on the FMA pipe: a*one + b, one==1 but unprovable by ptxas
__device__ __forceinline__ uint32_t addf(uint32_t a, uint32_t b, uint32_t one) {
    uint32_t r;
    asm("mad.lo.u32 %0, %1, %2, %3;" : "=r"(r) : "r"(a), "r"(one), "r"(b));
    return r;
}

// ---------- threefry2x32, key=(0,42), counter (0,c1) ----------
// Returns float BITS of 1+u: ((o0^o1)>>9) | 0x3f800000, tail folded into
// 2 umulhi (fma) + 1 LOP3 (alu).
// ks0 = 0, ks1 = 42, ks2 = 0x1BD11BDA ^ 0 ^ 42 = 0x1BD11BF0
__device__ __forceinline__ uint32_t tf_fbits_0_42(uint32_t c1, uint32_t one,
                                                  uint32_t k23) {
    const uint32_t ks1 = 42u;
    const uint32_t ks2 = 0x1BD11BF0u;
    uint32_t x1 = c1 + ks1;
    uint32_t x0 = x1;                 // round-1 add with x0 = c0+ks0 = 0
    x1 = __funnelshift_l(x1, x1, 13) ^ x0;
#define R(r) { x0 = addf(x1, x0, one); x1 = __funnelshift_l(x1, x1, (r)) ^ x0; }
#define INJR(ksA, ksB, r) { uint32_t x1p = x1 + (ksB);                 \
                            x0 = x0 + (ksA) + x1p; /* IADD3 */         \
                            x1 = __funnelshift_l(x1p, x1p, (r)) ^ x0; }
    R(15) R(26) R(6)                       // rounds 2-4
    INJR(ks1, ks2 + 1u, 17)                // inject1 + round 5
    R(29) R(16) R(24)                      // rounds 6-8
    INJR(ks2, 2u, 13)                      // inject2 + round 9   (ksB = ks0+2)
    R(15) R(26) R(6)                       // rounds 10-12
    { uint32_t x1p = x1 + (ks1 + 3u);      // inject3 (x0 key = ks0 = 0) + rd 13
      x0 = addf(x1p, x0, one);
      x1 = __funnelshift_l(x1p, x1p, 17) ^ x0; }
    R(29) R(16) R(24)                      // rounds 14-16
    INJR(ks1, ks2 + 4u, 13)                // inject4 + round 17
    R(15) R(26) R(6)                       // rounds 18-20
#undef R
#undef INJR
    x0 = x0 + ks2;                         // final injection
    x1 = x1 + 5u;                          // ks0 + 5
    uint32_t h0, h1, f;
    asm("mul.hi.u32 %0, %1, %2;" : "=r"(h0) : "r"(x0), "r"(k23));  // x0>>9
    asm("mul.hi.u32 %0, %1, %2;" : "=r"(h1) : "r"(x1), "r"(k23));  // x1>>9
    asm("lop3.b32 %0, %1, %2, %3, 0xBE;"                           // (h0^h1)|C
        : "=r"(f) : "r"(h0), "r"(h1), "r"(0x3f800000u));
    return f;
}

// ---------- gumbel in base-2 score domain, pure MUFU (verified R11) -------
// Input: float bits of 1+u. Returns L = log2(-log2(u)); caller's score is
// w = fmaf(x, rt2, -L). u=0: w -> -inf, never wins (reference's clamped
// lane also never wins, P ~ 1e-60).
__device__ __forceinline__ float log2_negl2_u(uint32_t fbits) {
    float u = __uint_as_float(fbits) - 1.0f;
    float l1 = __log2f(u);          // <= 0
    return __log2f(-l1);            // negation is a free operand modifier
}

__device__ __forceinline__ float argmax_pick(float2 v0, float2 v1, float rt2,
                                             uint32_t r0, uint32_t r1,
                                             uint32_t r2, uint32_t r3) {
    float wb = fmaf(v0.x, rt2, -log2_negl2_u(r0));
    float xb = v0.x;
    float w;
    w = fmaf(v0.y, rt2, -log2_negl2_u(r1)); if (w > wb) { wb = w; xb = v0.y; }
    w = fmaf(v1.x, rt2, -log2_negl2_u(r2)); if (w > wb) { wb = w; xb = v1.x; }
    w = fmaf(v1.y, rt2, -log2_negl2_u(r3)); if (w > wb) { wb = w; xb = v1.y; }
    return xb;
}

__global__ __launch_bounds__(256, 6)
void tdgs_pool_kernel(const float* __restrict__ x,
                      const float* __restrict__ temp,
                      float* __restrict__ out) {
    uint32_t one = gridDim.y;                       // == 1, opaque to ptxas
    uint32_t k23 = one << 23;                       // 2^23 in a register
    unsigned p = blockIdx.x * 256u + threadIdx.x;   // index over b in [0,8)
    unsigned wo = p % 56u;
    unsigned t1 = p / 56u;
    unsigned ho = t1 % 56u;
    unsigned t2 = t1 / 56u;          // b*128 + c, b < 8
    unsigned c  = t2 % 128u;

    // temperature: relu + 0.1; rt2 = (1/t)/ln2 shared by all 4 outputs
    float T  = temp[(c * 56u + ho) * 56u + wo];
    float tt = fmaxf(T, 0.0f) + 0.1f;
    float rt2 = __frcp_rn(tt) * 1.44269504088896340736f;

    unsigned xoff = (t2 * 112u + 2u * ho) * 112u + 2u * wo;
    unsigned base = p * 4u;

    // Hoisted patch loads: memory latency decoupled from compute.
    float2 v0[4], v1[4];
    #pragma unroll
    for (unsigned q = 0; q < 4; q++) {
        unsigned xo = xoff + q * QC;
        v0[q] = *reinterpret_cast<const float2*>(x + xo);
        v1[q] = *reinterpret_cast<const float2*>(x + xo + 112u);
    }

    #pragma unroll
    for (unsigned q = 0; q < 4; q++) {
        unsigned cb = base + q * QC;          // counter stride = 4*QO = QC
        uint32_t r0 = tf_fbits_0_42(cb + 0u, one, k23);
        uint32_t r1 = tf_fbits_0_42(cb + 1u, one, k23);
        uint32_t r2 = tf_fbits_0_42(cb + 2u, one, k23);
        uint32_t r3 = tf_fbits_0_42(cb + 3u, one, k23);
        out[p + q * QO] = argmax_pick(v0[q], v1[q], rt2, r0, r1, r2, r3);
    }
}

extern "C" void kernel_launch(void* const* d_in, const int* in_sizes, int n_in,
                              void* d_out, int out_size) {
    const float* x    = (const float*)d_in[0];   // (32,128,112,112) fp32
    const float* temp = (const float*)d_in[1];   // (128,56,56) fp32
    float* out        = (float*)d_out;           // (32,128,56,56) fp32

    // quads = 8*128*56*56 = 3,211,264 = 256 * 12544 exactly
    tdgs_pool_kernel<<<dim3(12544, 1, 1), 256>>>(x, temp, out);
}

// round 14
// speedup vs baseline: 1.0176x; 1.0176x over previous
#include <cuda_runtime.h>
#include <stdint.h>

// TDGSPooling2d: gumbel-softmax hard pooling over 2x2 patches (forward = argmax).
// out[b,c,ho,wo] = x_patch[argmax_k(x_patch[k]/temp[c,ho,wo] + g_k)]
// Noise: JAX partitionable threefry: bits[i] = o0^o1,
//   (o0,o1) = threefry2x32(key=(0,42), counter=(0,i))
//
// R14: R13 umulhi tail reverted (conclusively harmful). Structural ILP-8:
// the 16 hashes run as two groups of 8, ROUND-INTERLEAVED at source level
// (adjacent instructions always independent -> no intra-hash dependency
// bubbles on the alu pipe). __launch_bounds__(256,4): 64-reg budget,
// 50% occupancy, ILP makes up the warp-supply. Math identical to R12.

#define QC 12845056u   // x element stride AND counter stride per quarter (=4*QO)
#define QO 3211264u    // output element stride per batch-quarter (8*401408)

// add on the FMA pipe: a*one + b, one==1 but unprovable by ptxas
__device__ __forceinline__ uint32_t addf(uint32_t a, uint32_t b, uint32_t one) {
    uint32_t r;
    asm("mad.lo.u32 %0, %1, %2, %3;" : "=r"(r) : "r"(a), "r"(one), "r"(b));
    return r;
}

// ---------- 8-way interleaved threefry2x32, key=(0,42) ----------
// Counters: base0+{0..3}, base1+{0..3}. Returns o0^o1 per hash in r[8].
// ks0 = 0, ks1 = 42, ks2 = 0x1BD11BDA ^ 0 ^ 42 = 0x1BD11BF0
__device__ __forceinline__ void tf8_xor_0_42(uint32_t base0, uint32_t base1,
                                             uint32_t one, uint32_t* r) {
    const uint32_t ks1 = 42u;
    const uint32_t ks2 = 0x1BD11BF0u;
    uint32_t x0[8], x1[8];
    #pragma unroll
    for (int j = 0; j < 8; j++) {
        uint32_t c1 = (j < 4) ? (base0 + (unsigned)j) : (base1 + (unsigned)(j - 4));
        x1[j] = c1 + ks1;
        x0[j] = x1[j];                 // round-1 add with x0 = c0+ks0 = 0
        x1[j] = __funnelshift_l(x1[j], x1[j], 13) ^ x0[j];
    }
#define R8(rr) { _Pragma("unroll") for (int j = 0; j < 8; j++) {              \
        x0[j] = addf(x1[j], x0[j], one);                                      \
        x1[j] = __funnelshift_l(x1[j], x1[j], (rr)) ^ x0[j]; } }
#define INJ8(ksA, ksB, rr) { _Pragma("unroll") for (int j = 0; j < 8; j++) {  \
        uint32_t x1p = x1[j] + (ksB);                                         \
        x0[j] = x0[j] + (ksA) + x1p; /* IADD3 */                              \
        x1[j] = __funnelshift_l(x1p, x1p, (rr)) ^ x0[j]; } }
    R8(15) R8(26) R8(6)                    // rounds 2-4
    INJ8(ks1, ks2 + 1u, 17)                // inject1 + round 5
    R8(29) R8(16) R8(24)                   // rounds 6-8
    INJ8(ks2, 2u, 13)                      // inject2 + round 9   (ksB = ks0+2)
    R8(15) R8(26) R8(6)                    // rounds 10-12
    { _Pragma("unroll") for (int j = 0; j < 8; j++) {       // inject3 + rd 13
        uint32_t x1p = x1[j] + (ks1 + 3u);                  // (x0 key = 0)
        x0[j] = addf(x1p, x0[j], one);
        x1[j] = __funnelshift_l(x1p, x1p, 17) ^ x0[j]; } }
    R8(29) R8(16) R8(24)                   // rounds 14-16
    INJ8(ks1, ks2 + 4u, 13)                // inject4 + round 17
    R8(15) R8(26) R8(6)                    // rounds 18-20
#undef R8
#undef INJ8
    #pragma unroll
    for (int j = 0; j < 8; j++)
        r[j] = (x0[j] + ks2) ^ (x1[j] + 5u);   // final injection + output xor
}

// ---------- gumbel in base-2 score domain, pure MUFU (verified R11) -------
// Returns L = log2(-log2(u)); caller's score w = fmaf(x, rt2, -L).
// u=0: w -> -inf, never wins (reference's clamped lane also never wins).
__device__ __forceinline__ float log2_negl2_u(uint32_t bits) {
    float u = __uint_as_float((bits >> 9) | 0x3f800000u) - 1.0f;
    float l1 = __log2f(u);          // <= 0
    return __log2f(-l1);            // negation is a free operand modifier
}

__device__ __forceinline__ float argmax_pick(float2 v0, float2 v1, float rt2,
                                             uint32_t r0, uint32_t r1,
                                             uint32_t r2, uint32_t r3) {
    float wb = fmaf(v0.x, rt2, -log2_negl2_u(r0));
    float xb = v0.x;
    float w;
    w = fmaf(v0.y, rt2, -log2_negl2_u(r1)); if (w > wb) { wb = w; xb = v0.y; }
    w = fmaf(v1.x, rt2, -log2_negl2_u(r2)); if (w > wb) { wb = w; xb = v1.x; }
    w = fmaf(v1.y, rt2, -log2_negl2_u(r3)); if (w > wb) { wb = w; xb = v1.y; }
    return xb;
}

__global__ __launch_bounds__(256, 4)
void tdgs_pool_kernel(const float* __restrict__ x,
                      const float* __restrict__ temp,
                      float* __restrict__ out) {
    uint32_t one = gridDim.y;                       // == 1, opaque to ptxas
    unsigned p = blockIdx.x * 256u + threadIdx.x;   // index over b in [0,8)
    unsigned wo = p % 56u;
    unsigned t1 = p / 56u;
    unsigned ho = t1 % 56u;
    unsigned t2 = t1 / 56u;          // b*128 + c, b < 8
    unsigned c  = t2 % 128u;

    // temperature: relu + 0.1; rt2 = (1/t)/ln2 shared by all 4 outputs
    float T  = temp[(c * 56u + ho) * 56u + wo];
    float tt = fmaxf(T, 0.0f) + 0.1f;
    float rt2 = __frcp_rn(tt) * 1.44269504088896340736f;

    unsigned xoff = (t2 * 112u + 2u * ho) * 112u + 2u * wo;
    unsigned base = p * 4u;

    #pragma unroll
    for (unsigned h = 0; h < 2; h++) {              // halves: quarters 2h, 2h+1
        unsigned qa = 2u * h, qb = 2u * h + 1u;
        unsigned xa = xoff + qa * QC, xb_ = xoff + qb * QC;
        float2 a0 = *reinterpret_cast<const float2*>(x + xa);
        float2 a1 = *reinterpret_cast<const float2*>(x + xa + 112u);
        float2 b0 = *reinterpret_cast<const float2*>(x + xb_);
        float2 b1 = *reinterpret_cast<const float2*>(x + xb_ + 112u);

        uint32_t r[8];
        tf8_xor_0_42(base + qa * QC, base + qb * QC, one, r);

        out[p + qa * QO] = argmax_pick(a0, a1, rt2, r[0], r[1], r[2], r[3]);
        out[p + qb * QO] = argmax_pick(b0, b1, rt2, r[4], r[5], r[6], r[7]);
    }
}

extern "C" void kernel_launch(void* const* d_in, const int* in_sizes, int n_in,
                              void* d_out, int out_size) {
    const float* x    = (const float*)d_in[0];   // (32,128,112,112) fp32
    const float* temp = (const float*)d_in[1];   // (128,56,56) fp32
    float* out        = (float*)d_out;           // (32,128,56,56) fp32

    // quads = 8*128*56*56 = 3,211,264 = 256 * 12544 exactly
    tdgs_pool_kernel<<<dim3(12544, 1, 1), 256>>>(x, temp, out);
}

// round 15
// speedup vs baseline: 1.0289x; 1.0111x over previous
#include <cuda_runtime.h>
#include <stdint.h>

// TDGSPooling2d: gumbel-softmax hard pooling over 2x2 patches (forward = argmax).
// out[b,c,ho,wo] = x_patch[argmax_k(x_patch[k]/temp[c,ho,wo] + g_k)]
// Noise: JAX partitionable threefry: bits[i] = o0^o1,
//   (o0,o1) = threefry2x32(key=(0,42), counter=(0,i))
//
// R15: delete the per-hash bit-prep (SHF + LOP3, the last removable alu ops).
// Log-domain identity: with u' = r * 2^-32 (vs reference u = (r>>9)*2^-23),
//   L = log2(-log2(u')) = log2(32 - log2((float)r))
// i.e. I2F + MUFU + FADD + MUFU, no bit surgery. u' differs from u by
// <= ~1.2e-7 rel; the 32-l1 cancellation near u->1 mirrors R7's measured
// 3.3e-4 / 7-flip behavior (passed). r<512 lanes (ref clamps) never win.
// Structure otherwise identical to R12 (the best: 145.2us).

#define QC 12845056u   // x element stride AND counter stride per quarter (=4*QO)
#define QO 3211264u    // output element stride per batch-quarter (8*401408)

// add on the FMA pipe: a*one + b, one==1 but unprovable by ptxas
__device__ __forceinline__ uint32_t addf(uint32_t a, uint32_t b, uint32_t one) {
    uint32_t r;
    asm("mad.lo.u32 %0, %1, %2, %3;" : "=r"(r) : "r"(a), "r"(one), "r"(b));
    return r;
}

// ---------- threefry2x32, key=(0,42), counter (0,c1), return o0^o1 ----------
// ks0 = 0, ks1 = 42, ks2 = 0x1BD11BDA ^ 0 ^ 42 = 0x1BD11BF0
// Injection+round fusion: x1p = x1 + ksB; x0 = x0 + ksA + x1p (one IADD3);
// x1 = rotl(x1p, r) ^ x0.
__device__ __forceinline__ uint32_t tf_xor_0_42(uint32_t c1, uint32_t one) {
    const uint32_t ks1 = 42u;
    const uint32_t ks2 = 0x1BD11BF0u;
    uint32_t x1 = c1 + ks1;
    uint32_t x0 = x1;                 // round-1 add with x0 = c0+ks0 = 0
    x1 = __funnelshift_l(x1, x1, 13) ^ x0;
#define R(r) { x0 = addf(x1, x0, one); x1 = __funnelshift_l(x1, x1, (r)) ^ x0; }
#define INJR(ksA, ksB, r) { uint32_t x1p = x1 + (ksB);                 \
                            x0 = x0 + (ksA) + x1p; /* IADD3 */         \
                            x1 = __funnelshift_l(x1p, x1p, (r)) ^ x0; }
    R(15) R(26) R(6)                       // rounds 2-4
    INJR(ks1, ks2 + 1u, 17)                // inject1 + round 5
    R(29) R(16) R(24)                      // rounds 6-8
    INJR(ks2, 2u, 13)                      // inject2 + round 9   (ksB = ks0+2)
    R(15) R(26) R(6)                       // rounds 10-12
    { uint32_t x1p = x1 + (ks1 + 3u);      // inject3 (x0 key = ks0 = 0) + rd 13
      x0 = addf(x1p, x0, one);
      x1 = __funnelshift_l(x1p, x1p, 17) ^ x0; }
    R(29) R(16) R(24)                      // rounds 14-16
    INJR(ks1, ks2 + 4u, 13)                // inject4 + round 17
    R(15) R(26) R(6)                       // rounds 18-20
#undef R
#undef INJR
    x0 = x0 + ks2;                         // final injection
    x1 = x1 + 5u;                          // ks0 + 5
    return x0 ^ x1;
}

// ---------- gumbel score term, log-domain, no bit-prep ----------
// L = log2(-log2(u')) with u' = r * 2^-32:
//   bf  = (float)r          [I2F, off the alu pipe]
//   l1  = __log2f(bf)       [MUFU]
//   nl2 = 32 - l1           [FADD]  (= -log2(u') > 0)
//   L   = __log2f(nl2)      [MUFU]
// r=0: bf=0 -> l1=-inf -> nl2=+inf -> L=+inf -> w=-inf, never wins.
__device__ __forceinline__ float log2_negl2_u(uint32_t r) {
    float bf = (float)r;
    float nl2 = 32.0f - __log2f(bf);
    return __log2f(nl2);
}

__device__ __forceinline__ float argmax_pick(float2 v0, float2 v1, float rt2,
                                             uint32_t r0, uint32_t r1,
                                             uint32_t r2, uint32_t r3) {
    float wb = fmaf(v0.x, rt2, -log2_negl2_u(r0));
    float xb = v0.x;
    float w;
    w = fmaf(v0.y, rt2, -log2_negl2_u(r1)); if (w > wb) { wb = w; xb = v0.y; }
    w = fmaf(v1.x, rt2, -log2_negl2_u(r2)); if (w > wb) { wb = w; xb = v1.x; }
    w = fmaf(v1.y, rt2, -log2_negl2_u(r3)); if (w > wb) { wb = w; xb = v1.y; }
    return xb;
}

__global__ __launch_bounds__(256, 6)
void tdgs_pool_kernel(const float* __restrict__ x,
                      const float* __restrict__ temp,
                      float* __restrict__ out) {
    uint32_t one = gridDim.y;                       // == 1, opaque to ptxas
    unsigned p = blockIdx.x * 256u + threadIdx.x;   // index over b in [0,8)
    unsigned wo = p % 56u;
    unsigned t1 = p / 56u;
    unsigned ho = t1 % 56u;
    unsigned t2 = t1 / 56u;          // b*128 + c, b < 8
    unsigned c  = t2 % 128u;

    // temperature: relu + 0.1; rt2 = (1/t)/ln2 shared by all 4 outputs
    float T  = temp[(c * 56u + ho) * 56u + wo];
    float tt = fmaxf(T, 0.0f) + 0.1f;
    float rt2 = __frcp_rn(tt) * 1.44269504088896340736f;

    unsigned xoff = (t2 * 112u + 2u * ho) * 112u + 2u * wo;
    unsigned base = p * 4u;

    // Hoisted patch loads: memory latency decoupled from compute.
    float2 v0[4], v1[4];
    #pragma unroll
    for (unsigned q = 0; q < 4; q++) {
        unsigned xo = xoff + q * QC;
        v0[q] = *reinterpret_cast<const float2*>(x + xo);
        v1[q] = *reinterpret_cast<const float2*>(x + xo + 112u);
    }

    #pragma unroll
    for (unsigned q = 0; q < 4; q++) {
        unsigned cb = base + q * QC;          // counter stride = 4*QO = QC
        uint32_t r0 = tf_xor_0_42(cb + 0u, one);
        uint32_t r1 = tf_xor_0_42(cb + 1u, one);
        uint32_t r2 = tf_xor_0_42(cb + 2u, one);
        uint32_t r3 = tf_xor_0_42(cb + 3u, one);
        out[p + q * QO] = argmax_pick(v0[q], v1[q], rt2, r0, r1, r2, r3);
    }
}

extern "C" void kernel_launch(void* const* d_in, const int* in_sizes, int n_in,
                              void* d_out, int out_size) {
    const float* x    = (const float*)d_in[0];   // (32,128,112,112) fp32
    const float* temp = (const float*)d_in[1];   // (128,56,56) fp32
    float* out        = (float*)d_out;           // (32,128,56,56) fp32

    // quads = 8*128*56*56 = 3,211,264 = 256 * 12544 exactly
    tdgs_pool_kernel<<<dim3(12544, 1, 1), 256>>>(x, temp, out);
}

// round 16
// speedup vs baseline: 1.0307x; 1.0018x over previous
#include <cuda_runtime.h>
#include <stdint.h>

// TDGSPooling2d: gumbel-softmax hard pooling over 2x2 patches (forward = argmax).
// out[b,c,ho,wo] = x_patch[argmax_k(x_patch[k]/temp[c,ho,wo] + g_k)]
// Noise: JAX partitionable threefry: bits[i] = o0^o1,
//   (o0,o1) = threefry2x32(key=(0,42), counter=(0,i))
//
// R16: alu-pipe is the wall (calibrated ~44 alu/hash vs 41 irreducible).
//  (1) un-fuse injections: ALL non-round adds forced onto the fma pipe as
//      IMAD (addf). 3-input IADD3 was putting ~3 adds/hash back on alu.
//      alu/hash -> the hard 41 (20 SHF + 20 LOP3 + final XOR).
//  (2) geometry indexing: block (56,4), grid (1024,14); wo/ho/t2 from
//      builtins, no div/mod decode. 'one' now from gridDim.z (==1).
// Hash bits + gumbel identical to R15 -> rel_err exactly 6.03701e-4.

#define QC 12845056u   // x element stride AND counter stride per quarter (=4*QO)
#define QO 3211264u    // output element stride per batch-quarter (8*401408)

// add on the FMA pipe: a*one + b, one==1 but unprovable by ptxas
__device__ __forceinline__ uint32_t addf(uint32_t a, uint32_t b, uint32_t one) {
    uint32_t r;
    asm("mad.lo.u32 %0, %1, %2, %3;" : "=r"(r) : "r"(a), "r"(one), "r"(b));
    return r;
}

// ---------- threefry2x32, key=(0,42), counter (0,c1), return o0^o1 ----------
// ks0 = 0, ks1 = 42, ks2 = 0x1BD11BDA ^ 0 ^ 42 = 0x1BD11BF0
// Rounds: x0 += x1 (addf); x1 = rotl(x1,r) ^ x0  (SHF + LOP3, the alu core).
// ALL key injections via addf -> zero alu adds in the hash.
__device__ __forceinline__ uint32_t tf_xor_0_42(uint32_t c1, uint32_t one) {
    const uint32_t ks1 = 42u;
    const uint32_t ks2 = 0x1BD11BF0u;
    uint32_t x1 = addf(c1, ks1, one);
    uint32_t x0 = x1;                 // round-1 add with x0 = c0+ks0 = 0
    x1 = __funnelshift_l(x1, x1, 13) ^ x0;
#define R(r) { x0 = addf(x1, x0, one); x1 = __funnelshift_l(x1, x1, (r)) ^ x0; }
    R(15) R(26) R(6)                                    // rounds 2-4
    x0 = addf(x0, ks1, one);  x1 = addf(x1, ks2 + 1u, one);   // inject 1
    R(17) R(29) R(16) R(24)                             // rounds 5-8
    x0 = addf(x0, ks2, one);  x1 = addf(x1, 2u, one);         // inject 2
    R(13) R(15) R(26) R(6)                              // rounds 9-12
    /* x0 += ks0 (=0) */      x1 = addf(x1, ks1 + 3u, one);   // inject 3
    R(17) R(29) R(16) R(24)                             // rounds 13-16
    x0 = addf(x0, ks1, one);  x1 = addf(x1, ks2 + 4u, one);   // inject 4
    R(13) R(15) R(26) R(6)                              // rounds 17-20
#undef R
    x0 = addf(x0, ks2, one);  x1 = addf(x1, 5u, one);         // final inject
    return x0 ^ x1;
}

// ---------- gumbel score term, log-domain, no bit-prep (verified R15) -----
// L = log2(-log2(u')) with u' = r * 2^-32:
//   bf = (float)r; nl2 = 32 - __log2f(bf); L = __log2f(nl2)
// r=0: L=+inf -> w=-inf, never wins (reference's clamped lane also never wins).
__device__ __forceinline__ float log2_negl2_u(uint32_t r) {
    float bf = (float)r;
    float nl2 = 32.0f - __log2f(bf);
    return __log2f(nl2);
}

__device__ __forceinline__ float argmax_pick(float2 v0, float2 v1, float rt2,
                                             uint32_t r0, uint32_t r1,
                                             uint32_t r2, uint32_t r3) {
    float wb = fmaf(v0.x, rt2, -log2_negl2_u(r0));
    float xb = v0.x;
    float w;
    w = fmaf(v0.y, rt2, -log2_negl2_u(r1)); if (w > wb) { wb = w; xb = v0.y; }
    w = fmaf(v1.x, rt2, -log2_negl2_u(r2)); if (w > wb) { wb = w; xb = v1.x; }
    w = fmaf(v1.y, rt2, -log2_negl2_u(r3)); if (w > wb) { wb = w; xb = v1.y; }
    return xb;
}

__global__ __launch_bounds__(224, 7)
void tdgs_pool_kernel(const float* __restrict__ x,
                      const float* __restrict__ temp,
                      float* __restrict__ out) {
    uint32_t one = gridDim.z;                 // == 1, opaque to ptxas
    unsigned wo = threadIdx.x;                // [0,56)
    unsigned ho = blockIdx.y * 4u + threadIdx.y;   // [0,56)
    unsigned t2 = blockIdx.x;                 // b*128 + c, b < 8
    unsigned hw = ho * 56u + wo;
    unsigned p  = t2 * 3136u + hw;            // output index for b < 8
    unsigned c  = t2 & 127u;

    // temperature: relu + 0.1; rt2 = (1/t)/ln2 shared by all 4 outputs
    float T  = temp[c * 3136u + hw];
    float tt = fmaxf(T, 0.0f) + 0.1f;
    float rt2 = __frcp_rn(tt) * 1.44269504088896340736f;

    unsigned xoff = t2 * 12544u + ho * 224u + 2u * wo;
    unsigned base = p * 4u;

    // Hoisted patch loads: memory latency decoupled from compute.
    float2 v0[4], v1[4];
    #pragma unroll
    for (unsigned q = 0; q < 4; q++) {
        unsigned xo = xoff + q * QC;
        v0[q] = *reinterpret_cast<const float2*>(x + xo);
        v1[q] = *reinterpret_cast<const float2*>(x + xo + 112u);
    }

    #pragma unroll
    for (unsigned q = 0; q < 4; q++) {
        unsigned cb = base + q * QC;          // counter stride = 4*QO = QC
        uint32_t r0 = tf_xor_0_42(cb + 0u, one);
        uint32_t r1 = tf_xor_0_42(cb + 1u, one);
        uint32_t r2 = tf_xor_0_42(cb + 2u, one);
        uint32_t r3 = tf_xor_0_42(cb + 3u, one);
        out[p + q * QO] = argmax_pick(v0[q], v1[q], rt2, r0, r1, r2, r3);
    }
}

extern "C" void kernel_launch(void* const* d_in, const int* in_sizes, int n_in,
                              void* d_out, int out_size) {
    const float* x    = (const float*)d_in[0];   // (32,128,112,112) fp32
    const float* temp = (const float*)d_in[1];   // (128,56,56) fp32
    float* out        = (float*)d_out;           // (32,128,56,56) fp32

    // 1024 blocks.x (b<8 x 128 channels) x 14 blocks.y x (56,4) threads
    //   = 3,211,264 threads, 4 outputs each = 12,845,056 outputs exactly
    tdgs_pool_kernel<<<dim3(1024, 14, 1), dim3(56, 4, 1)>>>(x, temp, out);
}